// round 6
// baseline (speedup 1.0000x reference)
#include <cuda_runtime.h>
#include <cuda_bf16.h>
#include <cstdint>

#define B_ 8192
#define C_ 64
#define K_ 256
#define D_ 64
#define BTILE 128
#define NTILES 4096
#define NBLK 148

// ---------------- scratch (static __device__) ----------------
__device__ float g_val[B_ * C_];
__device__ int   g_idx[B_ * C_];
__device__ float g_sum[C_];
__device__ float g_sumsq[C_];

__device__ __forceinline__ unsigned fkey(float f) {
    unsigned u = __float_as_uint(f);
    return (u & 0x80000000u) ? ~u : (u | 0x80000000u);
}
__device__ __forceinline__ float fkey_inv(unsigned key) {
    unsigned u = (key & 0x80000000u) ? (key ^ 0x80000000u) : ~key;
    return __uint_as_float(u);
}
__device__ __forceinline__ uint32_t smem_u32(const void* p) {
    uint32_t a;
    asm("{ .reg .u64 t; cvta.to.shared.u64 t, %1; cvt.u32.u64 %0, t; }" : "=r"(a) : "l"(p));
    return a;
}

#define LDSM_X4(r0, r1, r2, r3, addr) \
    asm volatile("ldmatrix.sync.aligned.m8n8.x4.shared.b16 {%0,%1,%2,%3}, [%4];" \
        : "=r"(r0), "=r"(r1), "=r"(r2), "=r"(r3) : "r"(addr))
#define MMA_BF16(c, a, b0, b1) \
    asm volatile("mma.sync.aligned.m16n8k16.row.col.f32.bf16.bf16.f32 " \
        "{%0,%1,%2,%3}, {%4,%5,%6,%7}, {%8,%9}, {%0,%1,%2,%3};" \
        : "+f"((c)[0]), "+f"((c)[1]), "+f"((c)[2]), "+f"((c)[3]) \
        : "r"((a)[0]), "r"((a)[1]), "r"((a)[2]), "r"((a)[3]), "r"(b0), "r"(b1))

__device__ __forceinline__ void split3(float x, uint16_t& h, uint16_t& m, uint16_t& l) {
    __nv_bfloat16 bh = __float2bfloat16_rn(x);
    float r1 = x - __bfloat162float(bh);
    __nv_bfloat16 bm = __float2bfloat16_rn(r1);
    float r2 = r1 - __bfloat162float(bm);
    __nv_bfloat16 bl = __float2bfloat16_rn(r2);
    h = __bfloat16_as_ushort(bh);
    m = __bfloat16_as_ushort(bm);
    l = __bfloat16_as_ushort(bl);
}

// ---------------- smem layout (bytes) ----------------
#define SM_RED   0
#define SM_WSUM  4096
#define SM_A     8192
#define SM_B     (8192 + 49152)
#define SM_TOTAL (8192 + 49152 + 98304)   // 155648
#define A_PART   16384
#define B_PART   32768

__global__ void init_kernel() {
    int t = threadIdx.x;
    if (t < C_) { g_sum[t] = 0.f; g_sumsq[t] = 0.f; }
}

__device__ __forceinline__ uint32_t sw_off(int row, int cbyte) {
    return (uint32_t)(row * 128 + (cbyte ^ ((row & 7) << 4)));
}

__global__ void __launch_bounds__(512, 1)
score_kernel(const float* __restrict__ inp, const float* __restrict__ cent,
             const float* __restrict__ gamma) {
    extern __shared__ char smem[];
    const int tid  = threadIdx.x;
    const int lane = tid & 31;
    const int wid  = tid >> 5;
    const int warpM = wid & 7;
    const int warpN = wid >> 3;

    const uint32_t smem_base = smem_u32(smem);
    const uint32_t sA = smem_base + SM_A;
    const uint32_t sB = smem_base + SM_B;

    const int arow = warpM * 16 + (lane & 15);
    const uint32_t aoff0 = (uint32_t)(arow * 128);
    const uint32_t aswz = (uint32_t)((arow & 7) << 4);
    const int brow = warpN * 128 + (lane & 15);
    const uint32_t boff0 = (uint32_t)(brow * 128);
    const uint32_t bswz = (uint32_t)((brow & 7) << 4);
    const uint32_t lane16 = (uint32_t)(lane & 16);

    const int T0 = (blockIdx.x * NTILES) / NBLK;
    const int T1 = ((blockIdx.x + 1) * NTILES) / NBLK;

    int cur_c = -1;
    bool useMax = true;

    for (int T = T0; T < T1; T++) {
        const int c  = T >> 6;
        const int b0 = (T & 63) * BTILE;

        // ---- (re)fill B on channel change ----
        if (c != cur_c) {
            __syncthreads();
            cur_c = c;
            useMax = (gamma[c] >= 0.f);
            const float* Bb = cent + (size_t)c * (K_ * D_);
            for (int t = tid; t < K_ * 16; t += 512) {
                int r = t >> 4;
                int d = (t & 15) << 2;
                float4 v = *(const float4*)(Bb + (size_t)r * D_ + d);
                uint16_t h[4], m[4], l[4];
                split3(v.x, h[0], m[0], l[0]);
                split3(v.y, h[1], m[1], l[1]);
                split3(v.z, h[2], m[2], l[2]);
                split3(v.w, h[3], m[3], l[3]);
                uint32_t o = sw_off(r, d * 2);
                *(uint64_t*)(smem + SM_B + o)              = (uint64_t)h[0] | ((uint64_t)h[1] << 16) | ((uint64_t)h[2] << 32) | ((uint64_t)h[3] << 48);
                *(uint64_t*)(smem + SM_B + B_PART + o)     = (uint64_t)m[0] | ((uint64_t)m[1] << 16) | ((uint64_t)m[2] << 32) | ((uint64_t)m[3] << 48);
                *(uint64_t*)(smem + SM_B + 2 * B_PART + o) = (uint64_t)l[0] | ((uint64_t)l[1] << 16) | ((uint64_t)l[2] << 32) | ((uint64_t)l[3] << 48);
            }
        }

        // ---- fill A tile ----
        {
            const float* Ab = inp + (size_t)b0 * (C_ * D_) + (size_t)c * D_;
            for (int t = tid; t < BTILE * 16; t += 512) {
                int r = t >> 4;
                int d = (t & 15) << 2;
                float4 v = *(const float4*)(Ab + (size_t)r * (C_ * D_) + d);
                uint16_t h[4], m[4], l[4];
                split3(v.x, h[0], m[0], l[0]);
                split3(v.y, h[1], m[1], l[1]);
                split3(v.z, h[2], m[2], l[2]);
                split3(v.w, h[3], m[3], l[3]);
                uint32_t o = sw_off(r, d * 2);
                *(uint64_t*)(smem + SM_A + o)              = (uint64_t)h[0] | ((uint64_t)h[1] << 16) | ((uint64_t)h[2] << 32) | ((uint64_t)h[3] << 48);
                *(uint64_t*)(smem + SM_A + A_PART + o)     = (uint64_t)m[0] | ((uint64_t)m[1] << 16) | ((uint64_t)m[2] << 32) | ((uint64_t)m[3] << 48);
                *(uint64_t*)(smem + SM_A + 2 * A_PART + o) = (uint64_t)l[0] | ((uint64_t)l[1] << 16) | ((uint64_t)l[2] << 32) | ((uint64_t)l[3] << 48);
            }
        }
        __syncthreads();

        // ---- MMA mainloop: 4-t groups, part-major MMA runs ----
        // Same-acc reuse distance = 8 MMA issues; 16 live B regs, no spills.
        float acc[16][4];
#pragma unroll
        for (int j = 0; j < 16; j++)
#pragma unroll
            for (int e = 0; e < 4; e++) acc[j][e] = 0.f;

#pragma unroll
        for (int ks = 0; ks < 4; ks++) {
            const uint32_t kcb = (uint32_t)(ks * 32) + lane16;
            uint32_t aH[4], aM[4], aL[4];
            {
                uint32_t addr = sA + aoff0 + (kcb ^ aswz);
                LDSM_X4(aH[0], aH[1], aH[2], aH[3], addr);
                LDSM_X4(aM[0], aM[1], aM[2], aM[3], addr + A_PART);
                LDSM_X4(aL[0], aL[1], aL[2], aL[3], addr + 2 * A_PART);
            }
            const uint32_t baddr = sB + boff0 + (kcb ^ bswz);
#pragma unroll
            for (int tg = 0; tg < 2; tg++) {
                const uint32_t ga = baddr + (uint32_t)(tg * 8192);
                uint32_t bf[4][4];
                // ---- B-hi group: pairs with aH, aM, aL ----
#pragma unroll
                for (int i = 0; i < 4; i++)
                    LDSM_X4(bf[i][0], bf[i][1], bf[i][2], bf[i][3], ga + (uint32_t)(i * 2048));
#pragma unroll
                for (int i = 0; i < 4; i++) {
                    int t = tg * 4 + i;
                    MMA_BF16(acc[2 * t],     aH, bf[i][0], bf[i][2]);
                    MMA_BF16(acc[2 * t + 1], aH, bf[i][1], bf[i][3]);
                }
#pragma unroll
                for (int i = 0; i < 4; i++) {
                    int t = tg * 4 + i;
                    MMA_BF16(acc[2 * t],     aM, bf[i][0], bf[i][2]);
                    MMA_BF16(acc[2 * t + 1], aM, bf[i][1], bf[i][3]);
                }
#pragma unroll
                for (int i = 0; i < 4; i++) {
                    int t = tg * 4 + i;
                    MMA_BF16(acc[2 * t],     aL, bf[i][0], bf[i][2]);
                    MMA_BF16(acc[2 * t + 1], aL, bf[i][1], bf[i][3]);
                }
                // ---- B-mid group: pairs with aH, aM ----
#pragma unroll
                for (int i = 0; i < 4; i++)
                    LDSM_X4(bf[i][0], bf[i][1], bf[i][2], bf[i][3], ga + B_PART + (uint32_t)(i * 2048));
#pragma unroll
                for (int i = 0; i < 4; i++) {
                    int t = tg * 4 + i;
                    MMA_BF16(acc[2 * t],     aH, bf[i][0], bf[i][2]);
                    MMA_BF16(acc[2 * t + 1], aH, bf[i][1], bf[i][3]);
                }
#pragma unroll
                for (int i = 0; i < 4; i++) {
                    int t = tg * 4 + i;
                    MMA_BF16(acc[2 * t],     aM, bf[i][0], bf[i][2]);
                    MMA_BF16(acc[2 * t + 1], aM, bf[i][1], bf[i][3]);
                }
                // ---- B-lo group: pairs with aH ----
#pragma unroll
                for (int i = 0; i < 4; i++)
                    LDSM_X4(bf[i][0], bf[i][1], bf[i][2], bf[i][3], ga + 2 * B_PART + (uint32_t)(i * 2048));
#pragma unroll
                for (int i = 0; i < 4; i++) {
                    int t = tg * 4 + i;
                    MMA_BF16(acc[2 * t],     aH, bf[i][0], bf[i][2]);
                    MMA_BF16(acc[2 * t + 1], aH, bf[i][1], bf[i][3]);
                }
            }
        }

        // ---- epilogue ----
        unsigned long long best[2] = {0ull, 0ull};
        float s = 0.f, s2 = 0.f;
#pragma unroll
        for (int j = 0; j < 16; j++) {
#pragma unroll
            for (int e = 0; e < 4; e++) {
                float v = acc[j][e];
                s += v;
                s2 = fmaf(v, v, s2);
                int k = warpN * 128 + j * 8 + 2 * (lane & 3) + (e & 1);
                unsigned key = fkey(v);
                if (!useMax) key = ~key;
                unsigned long long p = ((unsigned long long)key << 32) | (unsigned)(255 - k);
                int r = (e >> 1);
                best[r] = (p > best[r]) ? p : best[r];
            }
        }
#pragma unroll
        for (int sh = 1; sh <= 2; sh <<= 1) {
            unsigned long long o0 = __shfl_xor_sync(0xffffffffu, best[0], sh);
            unsigned long long o1 = __shfl_xor_sync(0xffffffffu, best[1], sh);
            best[0] = (o0 > best[0]) ? o0 : best[0];
            best[1] = (o1 > best[1]) ? o1 : best[1];
        }
        unsigned long long* red = (unsigned long long*)(smem + SM_RED);
        if ((lane & 3) == 0) {
            int rl = warpM * 16 + (lane >> 2);
            red[warpN * 128 + rl] = best[0];
            red[warpN * 128 + rl + 8] = best[1];
        }
#pragma unroll
        for (int sh = 16; sh > 0; sh >>= 1) {
            s  += __shfl_xor_sync(0xffffffffu, s,  sh);
            s2 += __shfl_xor_sync(0xffffffffu, s2, sh);
        }
        float* wsum = (float*)(smem + SM_WSUM);
        if (lane == 0) { wsum[wid] = s; wsum[16 + wid] = s2; }
        __syncthreads();

        if (tid < BTILE) {
            unsigned long long p0 = red[tid];
            unsigned long long p1 = red[128 + tid];
            unsigned long long p = (p1 > p0) ? p1 : p0;
            unsigned key = (unsigned)(p >> 32);
            float v = fkey_inv(useMax ? key : ~key);
            int b = b0 + tid;
            g_val[(size_t)b * C_ + c] = v;
            g_idx[(size_t)b * C_ + c] = 255 - (int)(p & 0xFFu);
        }
        if (tid == 0) {
            float t1 = 0.f, t2 = 0.f;
#pragma unroll
            for (int w = 0; w < 16; w++) { t1 += wsum[w]; t2 += wsum[16 + w]; }
            atomicAdd(&g_sum[c], t1);
            atomicAdd(&g_sumsq[c], t2);
        }
        __syncthreads();
    }
}

// ---------------- finalize: BN affine + emit ----------------
__global__ void finalize_kernel(const float* __restrict__ gamma,
                                const float* __restrict__ beta,
                                float* __restrict__ out_codes,
                                float* __restrict__ out_mse) {
    int tid = blockIdx.x * 256 + threadIdx.x;
    if (tid >= B_ * C_) return;
    int c = tid & (C_ - 1);
    const float Ninv = 1.f / ((float)B_ * (float)K_);
    float mean = g_sum[c] * Ninv;
    float var  = fmaf(-mean, mean, g_sumsq[c] * Ninv);
    float scale = gamma[c] * rsqrtf(var + 1e-5f);
    float shift = fmaf(-mean, scale, beta[c]);
    out_codes[tid] = (float)g_idx[tid];
    out_mse[tid]   = fmaf(g_val[tid], scale, shift);
}

__global__ void copy_kernel(const float4* __restrict__ src,
                            float4* __restrict__ dst, int n4) {
    int i = blockIdx.x * blockDim.x + threadIdx.x;
    if (i < n4) dst[i] = src[i];
}

extern "C" void kernel_launch(void* const* d_in, const int* in_sizes, int n_in,
                              void* d_out, int out_size) {
    const float* inp   = (const float*)d_in[0];
    const float* cent  = (const float*)d_in[1];
    const float* gamma = (const float*)d_in[2];
    const float* beta  = (const float*)d_in[3];
    float* out = (float*)d_out;

    cudaFuncSetAttribute(score_kernel,
                         cudaFuncAttributeMaxDynamicSharedMemorySize, SM_TOTAL);

    init_kernel<<<1, 64>>>();

    score_kernel<<<NBLK, 512, SM_TOTAL>>>(inp, cent, gamma);

    finalize_kernel<<<(B_ * C_ + 255) / 256, 256>>>(gamma, beta,
                                                    out, out + B_ * C_);

    if (out_size >= 2 * B_ * C_ + C_ * K_ * D_) {
        int n4 = (C_ * K_ * D_) / 4;
        copy_kernel<<<(n4 + 255) / 256, 256>>>((const float4*)cent,
                                               (float4*)(out + 2 * B_ * C_), n4);
    }
}

// round 7
// speedup vs baseline: 1.4274x; 1.4274x over previous
#include <cuda_runtime.h>
#include <cuda_fp16.h>
#include <cstdint>

#define B_ 8192
#define C_ 64
#define K_ 256
#define D_ 64
#define BTILE 128
#define NTILES 4096
#define NBLK 148

// ---------------- scratch (static __device__) ----------------
__device__ float g_val[B_ * C_];
__device__ int   g_idx[B_ * C_];
__device__ float g_sum[C_];
__device__ float g_sumsq[C_];

__device__ __forceinline__ unsigned fkey(float f) {
    unsigned u = __float_as_uint(f);
    return (u & 0x80000000u) ? ~u : (u | 0x80000000u);
}
__device__ __forceinline__ float fkey_inv(unsigned key) {
    unsigned u = (key & 0x80000000u) ? (key ^ 0x80000000u) : ~key;
    return __uint_as_float(u);
}
__device__ __forceinline__ uint32_t smem_u32(const void* p) {
    uint32_t a;
    asm("{ .reg .u64 t; cvta.to.shared.u64 t, %1; cvt.u32.u64 %0, t; }" : "=r"(a) : "l"(p));
    return a;
}

#define LDSM_X4(r0, r1, r2, r3, addr) \
    asm volatile("ldmatrix.sync.aligned.m8n8.x4.shared.b16 {%0,%1,%2,%3}, [%4];" \
        : "=r"(r0), "=r"(r1), "=r"(r2), "=r"(r3) : "r"(addr))
#define MMA_F16(c, a, b0, b1) \
    asm volatile("mma.sync.aligned.m16n8k16.row.col.f32.f16.f16.f32 " \
        "{%0,%1,%2,%3}, {%4,%5,%6,%7}, {%8,%9}, {%0,%1,%2,%3};" \
        : "+f"((c)[0]), "+f"((c)[1]), "+f"((c)[2]), "+f"((c)[3]) \
        : "r"((a)[0]), "r"((a)[1]), "r"((a)[2]), "r"((a)[3]), "r"(b0), "r"(b1))

// fp16 2-term scaled split: x = h + 2^-11 * l + O(2^-23 x)
__device__ __forceinline__ void split2(float x, uint16_t& h, uint16_t& l) {
    __half hh = __float2half_rn(x);
    float r = x - __half2float(hh);          // exact
    __half ll = __float2half_rn(r * 2048.0f);
    h = __half_as_ushort(hh);
    l = __half_as_ushort(ll);
}

// ---------------- smem layout (bytes) ----------------
#define SM_RED   0                       // u64[2][128]
#define SM_WSUM  4096                    // f32[32]
#define SM_A     8192                    // 2 x 16384
#define SM_B     (8192 + 32768)          // 2 x 32768
#define SM_TOTAL (8192 + 32768 + 65536)  // 106496
#define A_PART   16384
#define B_PART   32768

__global__ void init_kernel() {
    int t = threadIdx.x;
    if (t < C_) { g_sum[t] = 0.f; g_sumsq[t] = 0.f; }
}

__device__ __forceinline__ uint32_t sw_off(int row, int cbyte) {
    return (uint32_t)(row * 128 + (cbyte ^ ((row & 7) << 4)));
}

__global__ void __launch_bounds__(512, 1)
score_kernel(const float* __restrict__ inp, const float* __restrict__ cent,
             const float* __restrict__ gamma) {
    extern __shared__ char smem[];
    const int tid  = threadIdx.x;
    const int lane = tid & 31;
    const int wid  = tid >> 5;
    const int warpM = wid & 7;
    const int warpN = wid >> 3;

    const uint32_t smem_base = smem_u32(smem);
    const uint32_t sA = smem_base + SM_A;
    const uint32_t sB = smem_base + SM_B;

    const int arow = warpM * 16 + (lane & 15);
    const uint32_t aoff0 = (uint32_t)(arow * 128);
    const uint32_t aswz = (uint32_t)((arow & 7) << 4);
    const int brow = warpN * 128 + (lane & 15);
    const uint32_t boff0 = (uint32_t)(brow * 128);
    const uint32_t bswz = (uint32_t)((brow & 7) << 4);
    const uint32_t lane16 = (uint32_t)(lane & 16);

    const int T0 = (blockIdx.x * NTILES) / NBLK;
    const int T1 = ((blockIdx.x + 1) * NTILES) / NBLK;

    int cur_c = -1;
    bool useMax = true;

    for (int T = T0; T < T1; T++) {
        const int c  = T >> 6;
        const int b0 = (T & 63) * BTILE;

        // ---- (re)fill B on channel change: 2-part fp16 split ----
        if (c != cur_c) {
            __syncthreads();
            cur_c = c;
            useMax = (gamma[c] >= 0.f);
            const float* Bb = cent + (size_t)c * (K_ * D_);
            for (int t = tid; t < K_ * 16; t += 512) {
                int r = t >> 4;
                int d = (t & 15) << 2;
                float4 v = *(const float4*)(Bb + (size_t)r * D_ + d);
                uint16_t h[4], l[4];
                split2(v.x, h[0], l[0]);
                split2(v.y, h[1], l[1]);
                split2(v.z, h[2], l[2]);
                split2(v.w, h[3], l[3]);
                uint32_t o = sw_off(r, d * 2);
                *(uint64_t*)(smem + SM_B + o)          = (uint64_t)h[0] | ((uint64_t)h[1] << 16) | ((uint64_t)h[2] << 32) | ((uint64_t)h[3] << 48);
                *(uint64_t*)(smem + SM_B + B_PART + o) = (uint64_t)l[0] | ((uint64_t)l[1] << 16) | ((uint64_t)l[2] << 32) | ((uint64_t)l[3] << 48);
            }
        }

        // ---- fill A tile ----
        {
            const float* Ab = inp + (size_t)b0 * (C_ * D_) + (size_t)c * D_;
            for (int t = tid; t < BTILE * 16; t += 512) {
                int r = t >> 4;
                int d = (t & 15) << 2;
                float4 v = *(const float4*)(Ab + (size_t)r * (C_ * D_) + d);
                uint16_t h[4], l[4];
                split2(v.x, h[0], l[0]);
                split2(v.y, h[1], l[1]);
                split2(v.z, h[2], l[2]);
                split2(v.w, h[3], l[3]);
                uint32_t o = sw_off(r, d * 2);
                *(uint64_t*)(smem + SM_A + o)          = (uint64_t)h[0] | ((uint64_t)h[1] << 16) | ((uint64_t)h[2] << 32) | ((uint64_t)h[3] << 48);
                *(uint64_t*)(smem + SM_A + A_PART + o) = (uint64_t)l[0] | ((uint64_t)l[1] << 16) | ((uint64_t)l[2] << 32) | ((uint64_t)l[3] << 48);
            }
        }
        __syncthreads();

        // ---- preload A fragments for all 4 ksteps (both parts) ----
        uint32_t ah[4][4], al[4][4];
        uint32_t bko[4];
#pragma unroll
        for (int ks = 0; ks < 4; ks++) {
            uint32_t kcb = (uint32_t)(ks * 32) + lane16;
            uint32_t addr = sA + aoff0 + (kcb ^ aswz);
            LDSM_X4(ah[ks][0], ah[ks][1], ah[ks][2], ah[ks][3], addr);
            LDSM_X4(al[ks][0], al[ks][1], al[ks][2], al[ks][3], addr + A_PART);
            bko[ks] = kcb ^ bswz;
        }
        const uint32_t bbase = sB + boff0;

        // ---- MMA mainloop: 3 passes (hh -> master, lh+hl -> scaled temp) ----
        float acc[16][4];
#pragma unroll
        for (int j = 0; j < 16; j++)
#pragma unroll
            for (int e = 0; e < 4; e++) acc[j][e] = 0.f;

#pragma unroll
        for (int p = 0; p < 8; p++) {      // j-pair (two n8 blocks)
            float t1a[4] = {0.f, 0.f, 0.f, 0.f};
            float t1b[4] = {0.f, 0.f, 0.f, 0.f};
            const uint32_t pb = bbase + (uint32_t)(p * 2048);
#pragma unroll
            for (int ks = 0; ks < 4; ks++) {
                uint32_t b0r, b1r, b2r, b3r;
                LDSM_X4(b0r, b1r, b2r, b3r, pb + bko[ks]);
                MMA_F16(acc[2 * p],     ah[ks], b0r, b2r);   // hh
                MMA_F16(acc[2 * p + 1], ah[ks], b1r, b3r);
                MMA_F16(t1a, al[ks], b0r, b2r);              // lh
                MMA_F16(t1b, al[ks], b1r, b3r);
                LDSM_X4(b0r, b1r, b2r, b3r, pb + B_PART + bko[ks]);
                MMA_F16(t1a, ah[ks], b0r, b2r);              // hl
                MMA_F16(t1b, ah[ks], b1r, b3r);
            }
            const float cc = 4.8828125e-4f;   // 2^-11
#pragma unroll
            for (int e = 0; e < 4; e++) {
                acc[2 * p][e]     = fmaf(cc, t1a[e], acc[2 * p][e]);
                acc[2 * p + 1][e] = fmaf(cc, t1b[e], acc[2 * p + 1][e]);
            }
        }

        // ---- epilogue ----
        unsigned long long best[2] = {0ull, 0ull};
        float s = 0.f, s2 = 0.f;
#pragma unroll
        for (int j = 0; j < 16; j++) {
#pragma unroll
            for (int e = 0; e < 4; e++) {
                float v = acc[j][e];
                s += v;
                s2 = fmaf(v, v, s2);
                int k = warpN * 128 + j * 8 + 2 * (lane & 3) + (e & 1);
                unsigned key = fkey(v);
                if (!useMax) key = ~key;
                unsigned long long p = ((unsigned long long)key << 32) | (unsigned)(255 - k);
                int r = (e >> 1);
                best[r] = (p > best[r]) ? p : best[r];
            }
        }
#pragma unroll
        for (int sh = 1; sh <= 2; sh <<= 1) {
            unsigned long long o0 = __shfl_xor_sync(0xffffffffu, best[0], sh);
            unsigned long long o1 = __shfl_xor_sync(0xffffffffu, best[1], sh);
            best[0] = (o0 > best[0]) ? o0 : best[0];
            best[1] = (o1 > best[1]) ? o1 : best[1];
        }
        unsigned long long* red = (unsigned long long*)(smem + SM_RED);
        if ((lane & 3) == 0) {
            int rl = warpM * 16 + (lane >> 2);
            red[warpN * 128 + rl] = best[0];
            red[warpN * 128 + rl + 8] = best[1];
        }
#pragma unroll
        for (int sh = 16; sh > 0; sh >>= 1) {
            s  += __shfl_xor_sync(0xffffffffu, s,  sh);
            s2 += __shfl_xor_sync(0xffffffffu, s2, sh);
        }
        float* wsum = (float*)(smem + SM_WSUM);
        if (lane == 0) { wsum[wid] = s; wsum[16 + wid] = s2; }
        __syncthreads();

        if (tid < BTILE) {
            unsigned long long p0 = red[tid];
            unsigned long long p1 = red[128 + tid];
            unsigned long long p = (p1 > p0) ? p1 : p0;
            unsigned key = (unsigned)(p >> 32);
            float v = fkey_inv(useMax ? key : ~key);
            int b = b0 + tid;
            g_val[(size_t)b * C_ + c] = v;
            g_idx[(size_t)b * C_ + c] = 255 - (int)(p & 0xFFu);
        }
        if (tid == 0) {
            float t1 = 0.f, t2 = 0.f;
#pragma unroll
            for (int w = 0; w < 16; w++) { t1 += wsum[w]; t2 += wsum[16 + w]; }
            atomicAdd(&g_sum[c], t1);
            atomicAdd(&g_sumsq[c], t2);
        }
        __syncthreads();
    }
}

// ---------------- finalize: BN affine + emit ----------------
__global__ void finalize_kernel(const float* __restrict__ gamma,
                                const float* __restrict__ beta,
                                float* __restrict__ out_codes,
                                float* __restrict__ out_mse) {
    int tid = blockIdx.x * 256 + threadIdx.x;
    if (tid >= B_ * C_) return;
    int c = tid & (C_ - 1);
    const float Ninv = 1.f / ((float)B_ * (float)K_);
    float mean = g_sum[c] * Ninv;
    float var  = fmaf(-mean, mean, g_sumsq[c] * Ninv);
    float scale = gamma[c] * rsqrtf(var + 1e-5f);
    float shift = fmaf(-mean, scale, beta[c]);
    out_codes[tid] = (float)g_idx[tid];
    out_mse[tid]   = fmaf(g_val[tid], scale, shift);
}

__global__ void copy_kernel(const float4* __restrict__ src,
                            float4* __restrict__ dst, int n4) {
    int i = blockIdx.x * blockDim.x + threadIdx.x;
    if (i < n4) dst[i] = src[i];
}

extern "C" void kernel_launch(void* const* d_in, const int* in_sizes, int n_in,
                              void* d_out, int out_size) {
    const float* inp   = (const float*)d_in[0];
    const float* cent  = (const float*)d_in[1];
    const float* gamma = (const float*)d_in[2];
    const float* beta  = (const float*)d_in[3];
    float* out = (float*)d_out;

    cudaFuncSetAttribute(score_kernel,
                         cudaFuncAttributeMaxDynamicSharedMemorySize, SM_TOTAL);

    init_kernel<<<1, 64>>>();

    score_kernel<<<NBLK, 512, SM_TOTAL>>>(inp, cent, gamma);

    finalize_kernel<<<(B_ * C_ + 255) / 256, 256>>>(gamma, beta,
                                                    out, out + B_ * C_);

    if (out_size >= 2 * B_ * C_ + C_ * K_ * D_) {
        int n4 = (C_ * K_ * D_) / 4;
        copy_kernel<<<(n4 + 255) / 256, 256>>>((const float4*)cent,
                                               (float4*)(out + 2 * B_ * C_), n4);
    }
}

// round 9
// speedup vs baseline: 1.5805x; 1.1072x over previous
#include <cuda_runtime.h>
#include <cuda_fp16.h>
#include <cstdint>

#define B_ 8192
#define C_ 64
#define K_ 256
#define D_ 64
#define BTILE 64
#define NTILES 8192            // C_ * (B_/BTILE)
#define NBLK 296               // 2 blocks per SM, persistent

// ---------------- scratch (static __device__) ----------------
__device__ float g_val[B_ * C_];
__device__ int   g_idx[B_ * C_];
__device__ float g_sum[C_];
__device__ float g_sumsq[C_];

__device__ __forceinline__ unsigned fkey(float f) {
    unsigned u = __float_as_uint(f);
    return (u & 0x80000000u) ? ~u : (u | 0x80000000u);
}
__device__ __forceinline__ float fkey_inv(unsigned key) {
    unsigned u = (key & 0x80000000u) ? (key ^ 0x80000000u) : ~key;
    return __uint_as_float(u);
}
__device__ __forceinline__ uint32_t smem_u32(const void* p) {
    uint32_t a;
    asm("{ .reg .u64 t; cvta.to.shared.u64 t, %1; cvt.u32.u64 %0, t; }" : "=r"(a) : "l"(p));
    return a;
}

#define LDSM_X4(r0, r1, r2, r3, addr) \
    asm volatile("ldmatrix.sync.aligned.m8n8.x4.shared.b16 {%0,%1,%2,%3}, [%4];" \
        : "=r"(r0), "=r"(r1), "=r"(r2), "=r"(r3) : "r"(addr))
#define MMA_F16(c, a, b0, b1) \
    asm volatile("mma.sync.aligned.m16n8k16.row.col.f32.f16.f16.f32 " \
        "{%0,%1,%2,%3}, {%4,%5,%6,%7}, {%8,%9}, {%0,%1,%2,%3};" \
        : "+f"((c)[0]), "+f"((c)[1]), "+f"((c)[2]), "+f"((c)[3]) \
        : "r"((a)[0]), "r"((a)[1]), "r"((a)[2]), "r"((a)[3]), "r"(b0), "r"(b1))

// fp16 2-term scaled split: x = h + 2^-11 * l + O(2^-23 x)
__device__ __forceinline__ void split2(float x, uint16_t& h, uint16_t& l) {
    __half hh = __float2half_rn(x);
    float r = x - __half2float(hh);          // exact
    __half ll = __float2half_rn(r * 2048.0f);
    h = __half_as_ushort(hh);
    l = __half_as_ushort(ll);
}

// ---------------- smem layout (bytes), per 256-thread block ----------------
#define SM_RED   0                        // u64[2][64] = 1024
#define SM_WSUM  1024                     // f32[16]
#define SM_A     2048                     // 2 x 8192
#define SM_B     (2048 + 16384)           // 2 x 32768
#define SM_TOTAL (2048 + 16384 + 65536)   // 83968
#define A_PART   8192
#define B_PART   32768

__global__ void init_kernel() {
    int t = threadIdx.x;
    if (t < C_) { g_sum[t] = 0.f; g_sumsq[t] = 0.f; }
}

__device__ __forceinline__ uint32_t sw_off(int row, int cbyte) {
    return (uint32_t)(row * 128 + (cbyte ^ ((row & 7) << 4)));
}

__global__ void __launch_bounds__(256, 2)
score_kernel(const float* __restrict__ inp, const float* __restrict__ cent,
             const float* __restrict__ gamma) {
    extern __shared__ char smem[];
    const int tid  = threadIdx.x;
    const int lane = tid & 31;
    const int wid  = tid >> 5;
    const int warpM = wid & 3;        // rows 16*warpM .. +15
    const int warpN = wid >> 2;       // cols 128*warpN .. +127

    const uint32_t smem_base = smem_u32(smem);
    const uint32_t sA = smem_base + SM_A;
    const uint32_t sB = smem_base + SM_B;

    const int arow = warpM * 16 + (lane & 15);
    const uint32_t aoff0 = (uint32_t)(arow * 128);
    const uint32_t aswz = (uint32_t)((arow & 7) << 4);
    const int brow = warpN * 128 + (lane & 15);
    const uint32_t boff0 = (uint32_t)(brow * 128);
    const uint32_t bswz = (uint32_t)((brow & 7) << 4);
    const uint32_t lane16 = (uint32_t)(lane & 16);

    const int T0 = (blockIdx.x * NTILES) / NBLK;
    const int T1 = ((blockIdx.x + 1) * NTILES) / NBLK;

    int cur_c = -1;
    bool useMax = true;

    for (int T = T0; T < T1; T++) {
        const int c  = T >> 7;
        const int b0 = (T & 127) * BTILE;

        // ---- (re)fill B on channel change: 2-part fp16 split ----
        if (c != cur_c) {
            __syncthreads();
            cur_c = c;
            useMax = (gamma[c] >= 0.f);
            const float* Bb = cent + (size_t)c * (K_ * D_);
            for (int t = tid; t < K_ * 16; t += 256) {
                int r = t >> 4;
                int d = (t & 15) << 2;
                float4 v = *(const float4*)(Bb + (size_t)r * D_ + d);
                uint16_t h[4], l[4];
                split2(v.x, h[0], l[0]);
                split2(v.y, h[1], l[1]);
                split2(v.z, h[2], l[2]);
                split2(v.w, h[3], l[3]);
                uint32_t o = sw_off(r, d * 2);
                *(uint64_t*)(smem + SM_B + o)          = (uint64_t)h[0] | ((uint64_t)h[1] << 16) | ((uint64_t)h[2] << 32) | ((uint64_t)h[3] << 48);
                *(uint64_t*)(smem + SM_B + B_PART + o) = (uint64_t)l[0] | ((uint64_t)l[1] << 16) | ((uint64_t)l[2] << 32) | ((uint64_t)l[3] << 48);
            }
        }

        // ---- fill A tile (64 rows) ----
        {
            const float* Ab = inp + (size_t)b0 * (C_ * D_) + (size_t)c * D_;
            for (int t = tid; t < BTILE * 16; t += 256) {
                int r = t >> 4;
                int d = (t & 15) << 2;
                float4 v = *(const float4*)(Ab + (size_t)r * (C_ * D_) + d);
                uint16_t h[4], l[4];
                split2(v.x, h[0], l[0]);
                split2(v.y, h[1], l[1]);
                split2(v.z, h[2], l[2]);
                split2(v.w, h[3], l[3]);
                uint32_t o = sw_off(r, d * 2);
                *(uint64_t*)(smem + SM_A + o)          = (uint64_t)h[0] | ((uint64_t)h[1] << 16) | ((uint64_t)h[2] << 32) | ((uint64_t)h[3] << 48);
                *(uint64_t*)(smem + SM_A + A_PART + o) = (uint64_t)l[0] | ((uint64_t)l[1] << 16) | ((uint64_t)l[2] << 32) | ((uint64_t)l[3] << 48);
            }
        }
        __syncthreads();

        // ---- preload A fragments for all 4 ksteps (both parts) ----
        uint32_t ah[4][4], al[4][4];
        uint32_t bko[4];
#pragma unroll
        for (int ks = 0; ks < 4; ks++) {
            uint32_t kcb = (uint32_t)(ks * 32) + lane16;
            uint32_t addr = sA + aoff0 + (kcb ^ aswz);
            LDSM_X4(ah[ks][0], ah[ks][1], ah[ks][2], ah[ks][3], addr);
            LDSM_X4(al[ks][0], al[ks][1], al[ks][2], al[ks][3], addr + A_PART);
            bko[ks] = kcb ^ bswz;
        }
        const uint32_t bbase = sB + boff0;

        // ---- MMA mainloop: 3 passes (hh -> master, lh+hl -> scaled temp) ----
        float acc[16][4];
#pragma unroll
        for (int j = 0; j < 16; j++)
#pragma unroll
            for (int e = 0; e < 4; e++) acc[j][e] = 0.f;

#pragma unroll
        for (int p = 0; p < 8; p++) {
            float t1a[4] = {0.f, 0.f, 0.f, 0.f};
            float t1b[4] = {0.f, 0.f, 0.f, 0.f};
            const uint32_t pb = bbase + (uint32_t)(p * 2048);
#pragma unroll
            for (int ks = 0; ks < 4; ks++) {
                uint32_t b0r, b1r, b2r, b3r;
                LDSM_X4(b0r, b1r, b2r, b3r, pb + bko[ks]);
                MMA_F16(acc[2 * p],     ah[ks], b0r, b2r);   // hh
                MMA_F16(acc[2 * p + 1], ah[ks], b1r, b3r);
                MMA_F16(t1a, al[ks], b0r, b2r);              // lh
                MMA_F16(t1b, al[ks], b1r, b3r);
                LDSM_X4(b0r, b1r, b2r, b3r, pb + B_PART + bko[ks]);
                MMA_F16(t1a, ah[ks], b0r, b2r);              // hl
                MMA_F16(t1b, ah[ks], b1r, b3r);
            }
            const float cc = 4.8828125e-4f;   // 2^-11
#pragma unroll
            for (int e = 0; e < 4; e++) {
                acc[2 * p][e]     = fmaf(cc, t1a[e], acc[2 * p][e]);
                acc[2 * p + 1][e] = fmaf(cc, t1b[e], acc[2 * p + 1][e]);
            }
        }

        // ---- epilogue ----
        unsigned long long best[2] = {0ull, 0ull};
        float s = 0.f, s2 = 0.f;
#pragma unroll
        for (int j = 0; j < 16; j++) {
#pragma unroll
            for (int e = 0; e < 4; e++) {
                float v = acc[j][e];
                s += v;
                s2 = fmaf(v, v, s2);
                int k = warpN * 128 + j * 8 + 2 * (lane & 3) + (e & 1);
                unsigned key = fkey(v);
                if (!useMax) key = ~key;
                unsigned long long p = ((unsigned long long)key << 32) | (unsigned)(255 - k);
                int r = (e >> 1);
                best[r] = (p > best[r]) ? p : best[r];
            }
        }
#pragma unroll
        for (int sh = 1; sh <= 2; sh <<= 1) {
            unsigned long long o0 = __shfl_xor_sync(0xffffffffu, best[0], sh);
            unsigned long long o1 = __shfl_xor_sync(0xffffffffu, best[1], sh);
            best[0] = (o0 > best[0]) ? o0 : best[0];
            best[1] = (o1 > best[1]) ? o1 : best[1];
        }
        unsigned long long* red = (unsigned long long*)(smem + SM_RED);  // [2][64]
        if ((lane & 3) == 0) {
            int rl = warpM * 16 + (lane >> 2);
            red[warpN * 64 + rl] = best[0];
            red[warpN * 64 + rl + 8] = best[1];
        }
#pragma unroll
        for (int sh = 16; sh > 0; sh >>= 1) {
            s  += __shfl_xor_sync(0xffffffffu, s,  sh);
            s2 += __shfl_xor_sync(0xffffffffu, s2, sh);
        }
        float* wsum = (float*)(smem + SM_WSUM);
        if (lane == 0) { wsum[wid] = s; wsum[8 + wid] = s2; }
        __syncthreads();

        if (tid < BTILE) {
            unsigned long long p0 = red[tid];
            unsigned long long p1 = red[64 + tid];
            unsigned long long p = (p1 > p0) ? p1 : p0;
            unsigned key = (unsigned)(p >> 32);
            float v = fkey_inv(useMax ? key : ~key);
            int b = b0 + tid;
            g_val[(size_t)b * C_ + c] = v;
            g_idx[(size_t)b * C_ + c] = 255 - (int)(p & 0xFFu);
        }
        if (tid == 0) {
            float t1 = 0.f, t2 = 0.f;
#pragma unroll
            for (int w = 0; w < 8; w++) { t1 += wsum[w]; t2 += wsum[8 + w]; }
            atomicAdd(&g_sum[c], t1);
            atomicAdd(&g_sumsq[c], t2);
        }
        __syncthreads();
    }
}

// ---------------- finalize: BN affine + emit ----------------
__global__ void finalize_kernel(const float* __restrict__ gamma,
                                const float* __restrict__ beta,
                                float* __restrict__ out_codes,
                                float* __restrict__ out_mse) {
    int tid = blockIdx.x * 256 + threadIdx.x;
    if (tid >= B_ * C_) return;
    int c = tid & (C_ - 1);
    const float Ninv = 1.f / ((float)B_ * (float)K_);
    float mean = g_sum[c] * Ninv;
    float var  = fmaf(-mean, mean, g_sumsq[c] * Ninv);
    float scale = gamma[c] * rsqrtf(var + 1e-5f);
    float shift = fmaf(-mean, scale, beta[c]);
    out_codes[tid] = (float)g_idx[tid];
    out_mse[tid]   = fmaf(g_val[tid], scale, shift);
}

__global__ void copy_kernel(const float4* __restrict__ src,
                            float4* __restrict__ dst, int n4) {
    int i = blockIdx.x * blockDim.x + threadIdx.x;
    if (i < n4) dst[i] = src[i];
}

extern "C" void kernel_launch(void* const* d_in, const int* in_sizes, int n_in,
                              void* d_out, int out_size) {
    const float* inp   = (const float*)d_in[0];
    const float* cent  = (const float*)d_in[1];
    const float* gamma = (const float*)d_in[2];
    const float* beta  = (const float*)d_in[3];
    float* out = (float*)d_out;

    cudaFuncSetAttribute(score_kernel,
                         cudaFuncAttributeMaxDynamicSharedMemorySize, SM_TOTAL);

    init_kernel<<<1, 64>>>();

    score_kernel<<<NBLK, 256, SM_TOTAL>>>(inp, cent, gamma);

    finalize_kernel<<<(B_ * C_ + 255) / 256, 256>>>(gamma, beta,
                                                    out, out + B_ * C_);

    if (out_size >= 2 * B_ * C_ + C_ * K_ * D_) {
        int n4 = (C_ * K_ * D_) / 4;
        copy_kernel<<<(n4 + 255) / 256, 256>>>((const float4*)cent,
                                               (float4*)(out + 2 * B_ * C_), n4);
    }
}